// round 14
// baseline (speedup 1.0000x reference)
#include <cuda_runtime.h>

// Insert e into sorted (desc) top-4 registers t0>=t1>=t2>=t3.
__device__ __forceinline__ void ins4(float e, float& t0, float& t1, float& t2, float& t3)
{
    float c = e;
    float n0 = fmaxf(t0, c); c = fminf(t0, c);
    float n1 = fmaxf(t1, c); c = fminf(t1, c);
    float n2 = fmaxf(t2, c); c = fminf(t2, c);
    t3 = fmaxf(t3, c);
    t0 = n0; t1 = n1; t2 = n2;
}

__device__ __forceinline__ void acc_one(float v, float& s,
                                        float& t0, float& t1, float& t2, float& t3)
{
    float e = __expf(v);
    s += e;
    ins4(e, t0, t1, t2, t3);
}

__device__ __forceinline__ void ce(float& a, float& b) {
    float hi = fmaxf(a, b);
    float lo = fminf(a, b);
    a = hi; b = lo;
}

// Block = 256 threads (8 warps) = 64 rows.
//  Phase A: thread (row=tid>>2, g=tid&3): top4+sum for ONE group of 33, two independent
//           halves (17/16) then merged. LDS bank (4r+g+k) mod 32 conflict-free.
//  (stats/partials ALIAS the consumed corners buffer: saves 6.4KB -> 5 blocks/SM)
//  Phase B: warp (rh=w>>2, hq=w&3): rows rh*32+lane, hidden [16hq,16hq+16), 2 passes of 8.
//  Pre-reduce: 64 threads sum the 4 hidden-quarter partials + b2 -> sQv[row].
//  Phase C: coalesced float4: out = scores + sQv[row].
__global__ __launch_bounds__(256, 5)
void lqe_kernel(const float* __restrict__ scores,
                const float* __restrict__ corners,
                const float* __restrict__ gW1,
                const float* __restrict__ gb1,
                const float* __restrict__ gW2,
                const float* __restrict__ gb2,
                float* __restrict__ out,
                int rows)
{
    __shared__ __align__(16) float sBuf[64 * 132];   // corners; later stats/qp/qv
    __shared__ __align__(16) float sW1[20 * 64];     // 5120 B
    __shared__ __align__(16) float sB1[64];
    __shared__ __align__(16) float sW2[64];
    __shared__ float sB2;

    // alias layout inside sBuf after Phase A consumes the corners:
    //   stats: [0 .. 64*20)           pitch 20, 16B-aligned rows
    //   qp:    [1280 .. 1280+4*64)
    //   qv:    [1536 .. 1600)
    float* sStat = sBuf;
    float* sQp   = sBuf + 1280;
    float* sQv   = sBuf + 1536;

    const int tid  = threadIdx.x;
    const int row0 = blockIdx.x * 64;
    const int nr   = min(64, rows - row0);

    // ---------------- stage corners (coalesced float4) ----------------
    {
        const float4* src = (const float4*)(corners + (size_t)row0 * 132);
        float4* dst = (float4*)sBuf;
        if (nr == 64) {                       // 2112 float4 = 8.25 * 256
            #pragma unroll
            for (int j = 0; j < 8; j++) dst[j * 256 + tid] = src[j * 256 + tid];
            if (tid < 64) dst[2048 + tid] = src[2048 + tid];
        } else {
            int n4 = nr * 33;
            for (int i = tid; i < n4; i += 256) dst[i] = src[i];
        }
    }
    // ---------------- stage weights ----------------
    {
        const float4* w4 = (const float4*)gW1;
        float4* d4 = (float4*)sW1;
        #pragma unroll
        for (int j = 0; j < 2; j++) {
            int idx = j * 256 + tid;
            if (idx < 320) d4[idx] = w4[idx];
        }
        if (tid < 64)        sB1[tid] = gb1[tid];
        else if (tid < 128)  sW2[tid - 64] = gW2[tid - 64];
        if (tid == 0)        sB2 = gb2[0];
    }
    __syncthreads();

    // ---------------- Phase A: one group of 33 per thread, split 17/16 ----------------
    float p0, p1, p2, p3, mean;
    const int lrow = tid >> 2;
    const int g    = tid & 3;
    {
        const float* base = sBuf + lrow * 132 + 33 * g;

        float sa = 0.f, a0 = 0.f, a1 = 0.f, a2 = 0.f, a3 = 0.f;
        float sb = 0.f, b0 = 0.f, b1v = 0.f, b2v = 0.f, b3 = 0.f;

        #pragma unroll
        for (int k = 0; k < 16; k++) {
            acc_one(base[k],      sa, a0, a1, a2, a3);
            acc_one(base[17 + k], sb, b0, b1v, b2v, b3);
        }
        acc_one(base[16], sa, a0, a1, a2, a3);

        // merge two sorted-desc quads: top4 = sort(max(a_i, b_{3-i}))
        float u0 = fmaxf(a0, b3);
        float u1 = fmaxf(a1, b2v);
        float u2 = fmaxf(a2, b1v);
        float u3 = fmaxf(a3, b0);
        ce(u0, u2); ce(u1, u3); ce(u0, u1); ce(u2, u3);

        float inv = __frcp_rn(sa + sb);
        p0 = u0 * inv; p1 = u1 * inv; p2 = u2 * inv; p3 = u3 * inv;
        mean = 0.25f * ((p0 + p1) + (p2 + p3));
    }
    __syncthreads();   // all corner reads done before aliasing writes

    {
        float* so = sStat + lrow * 20 + 5 * g;
        so[0] = p0; so[1] = p1; so[2] = p2; so[3] = p3; so[4] = mean;
    }
    __syncthreads();

    // ---------------- Phase B: MLP ----------------
    {
        const int warp = tid >> 5;
        const int lane = tid & 31;
        const int rh   = warp >> 2;        // row half: 0 or 1
        const int hq   = warp & 3;         // hidden quarter: 0..3
        const int mrow = rh * 32 + lane;

        float st[20];
        {
            const float* sr = sStat + mrow * 20;   // 16B-aligned, conflict-free LDS.128
            float4 q0 = *(const float4*)(sr + 0);
            float4 q1 = *(const float4*)(sr + 4);
            float4 q2 = *(const float4*)(sr + 8);
            float4 q3 = *(const float4*)(sr + 12);
            float4 q4 = *(const float4*)(sr + 16);
            st[0]  = q0.x; st[1]  = q0.y; st[2]  = q0.z; st[3]  = q0.w;
            st[4]  = q1.x; st[5]  = q1.y; st[6]  = q1.z; st[7]  = q1.w;
            st[8]  = q2.x; st[9]  = q2.y; st[10] = q2.z; st[11] = q2.w;
            st[12] = q3.x; st[13] = q3.y; st[14] = q3.z; st[15] = q3.w;
            st[16] = q4.x; st[17] = q4.y; st[18] = q4.z; st[19] = q4.w;
        }

        float q = 0.f;
        #pragma unroll
        for (int pass = 0; pass < 2; pass++) {
            const int h0 = hq * 16 + pass * 8;     // warp-uniform
            float acc[8];
            {
                float4 ba = *(const float4*)(sB1 + h0);
                float4 bb = *(const float4*)(sB1 + h0 + 4);
                acc[0] = ba.x; acc[1] = ba.y; acc[2] = ba.z; acc[3] = ba.w;
                acc[4] = bb.x; acc[5] = bb.y; acc[6] = bb.z; acc[7] = bb.w;
            }
            #pragma unroll
            for (int d = 0; d < 20; d++) {
                float sd = st[d];
                float4 wa = *(const float4*)(sW1 + d * 64 + h0);
                float4 wb = *(const float4*)(sW1 + d * 64 + h0 + 4);
                acc[0] += sd * wa.x; acc[1] += sd * wa.y;
                acc[2] += sd * wa.z; acc[3] += sd * wa.w;
                acc[4] += sd * wb.x; acc[5] += sd * wb.y;
                acc[6] += sd * wb.z; acc[7] += sd * wb.w;
            }
            {
                float4 wa = *(const float4*)(sW2 + h0);
                float4 wb = *(const float4*)(sW2 + h0 + 4);
                q += fmaxf(acc[0], 0.f) * wa.x;
                q += fmaxf(acc[1], 0.f) * wa.y;
                q += fmaxf(acc[2], 0.f) * wa.z;
                q += fmaxf(acc[3], 0.f) * wa.w;
                q += fmaxf(acc[4], 0.f) * wb.x;
                q += fmaxf(acc[5], 0.f) * wb.y;
                q += fmaxf(acc[6], 0.f) * wb.z;
                q += fmaxf(acc[7], 0.f) * wb.w;
            }
        }
        sQp[hq * 64 + mrow] = q;
    }
    __syncthreads();

    // ---------------- pre-reduce partials: sQv[row] = sum of 4 + b2 ----------------
    if (tid < 64) {
        float qv = (sQp[tid] + sQp[64 + tid]) + (sQp[128 + tid] + sQp[192 + tid]) + sB2;
        sQv[tid] = qv;
    }
    __syncthreads();

    // ---------------- Phase C: out = scores + qv ----------------
    {
        const float4* s4 = (const float4*)(scores + (size_t)row0 * 80);
        float4*       o4 = (float4*)(out + (size_t)row0 * 80);
        if (nr == 64) {                       // 1280 float4 = 5 * 256
            #pragma unroll
            for (int j = 0; j < 5; j++) {
                int i = j * 256 + tid;
                float qv = sQv[i / 20];
                float4 v = s4[i];
                v.x += qv; v.y += qv; v.z += qv; v.w += qv;
                o4[i] = v;
            }
        } else {
            int n4 = nr * 20;
            for (int i = tid; i < n4; i += 256) {
                float qv = sQv[i / 20];
                float4 v = s4[i];
                v.x += qv; v.y += qv; v.z += qv; v.w += qv;
                o4[i] = v;
            }
        }
    }
}

extern "C" void kernel_launch(void* const* d_in, const int* in_sizes, int n_in,
                              void* d_out, int out_size) {
    const float* scores  = (const float*)d_in[0];
    const float* corners = (const float*)d_in[1];
    const float* W1      = (const float*)d_in[2];
    const float* b1      = (const float*)d_in[3];
    const float* W2      = (const float*)d_in[4];
    const float* b2      = (const float*)d_in[5];
    float* out = (float*)d_out;

    int rows = in_sizes[0] / 80;              // B*L
    int blocks = (rows + 63) / 64;
    lqe_kernel<<<blocks, 256>>>(scores, corners, W1, b1, W2, b2, out, rows);
}

// round 16
// speedup vs baseline: 1.5347x; 1.5347x over previous
#include <cuda_runtime.h>

// Insert e into sorted (desc) top-4 registers t0>=t1>=t2>=t3.
__device__ __forceinline__ void ins4(float e, float& t0, float& t1, float& t2, float& t3)
{
    float c = e;
    float n0 = fmaxf(t0, c); c = fminf(t0, c);
    float n1 = fmaxf(t1, c); c = fminf(t1, c);
    float n2 = fmaxf(t2, c); c = fminf(t2, c);
    t3 = fmaxf(t3, c);
    t0 = n0; t1 = n1; t2 = n2;
}

__device__ __forceinline__ void acc_one(float v, float& s,
                                        float& t0, float& t1, float& t2, float& t3)
{
    float e = __expf(v);
    s += e;
    ins4(e, t0, t1, t2, t3);
}

__device__ __forceinline__ void ce(float& a, float& b) {
    float hi = fmaxf(a, b);
    float lo = fminf(a, b);
    a = hi; b = lo;
}

// Block = 256 threads (8 warps) = 64 rows. (R13 structure: separate arrays, 4 CTAs/SM.)
//  Phase A: thread (row=tid>>2, g=tid&3): top4+sum for ONE group of 33, two independent
//           halves (17/16) then merged. LDS bank (4r+g+k) mod 32 conflict-free.
//  Phase B: warp (rh=w>>2, hq=w&3): rows rh*32+lane, hidden [16hq,16hq+16), 2 passes of 8.
//  Pre-reduce: 64 threads sum the 4 hidden-quarter partials + b2 -> sQv[row].
//  Phase C: coalesced float4 streaming: out = scores + sQv[row].
__global__ __launch_bounds__(256, 4)
void lqe_kernel(const float* __restrict__ scores,
                const float* __restrict__ corners,
                const float* __restrict__ gW1,
                const float* __restrict__ gb1,
                const float* __restrict__ gW2,
                const float* __restrict__ gb2,
                float* __restrict__ out,
                int rows)
{
    __shared__ __align__(16) float sC[64 * 132];     // 33792 B
    __shared__ __align__(16) float sW1[20 * 64];     //  5120 B
    __shared__ __align__(16) float sB1[64];
    __shared__ __align__(16) float sW2[64];
    __shared__ __align__(16) float sStat[64 * 20];   //  5120 B, pitch 20
    __shared__ float sQp[4 * 64];                    // per-hidden-quarter partials
    __shared__ float sQv[64];                        // reduced quality per row
    __shared__ float sB2;

    const int tid  = threadIdx.x;
    const int row0 = blockIdx.x * 64;
    const int nr   = min(64, rows - row0);

    // ---------------- stage corners (coalesced float4, streaming) ----------------
    {
        const float4* src = (const float4*)(corners + (size_t)row0 * 132);
        float4* dst = (float4*)sC;
        if (nr == 64) {                       // 2112 float4 = 8.25 * 256
            #pragma unroll
            for (int j = 0; j < 8; j++) dst[j * 256 + tid] = __ldcs(src + j * 256 + tid);
            if (tid < 64) dst[2048 + tid] = __ldcs(src + 2048 + tid);
        } else {
            int n4 = nr * 33;
            for (int i = tid; i < n4; i += 256) dst[i] = __ldcs(src + i);
        }
    }
    // ---------------- stage weights ----------------
    {
        const float4* w4 = (const float4*)gW1;
        float4* d4 = (float4*)sW1;
        #pragma unroll
        for (int j = 0; j < 2; j++) {
            int idx = j * 256 + tid;
            if (idx < 320) d4[idx] = w4[idx];
        }
        if (tid < 64)        sB1[tid] = gb1[tid];
        else if (tid < 128)  sW2[tid - 64] = gW2[tid - 64];
        if (tid == 0)        sB2 = gb2[0];
    }
    __syncthreads();

    // ---------------- Phase A: one group of 33 per thread, split 17/16 ----------------
    {
        const int lrow = tid >> 2;
        const int g    = tid & 3;
        if (lrow < nr) {
            const float* base = sC + lrow * 132 + 33 * g;

            float sa = 0.f, a0 = 0.f, a1 = 0.f, a2 = 0.f, a3 = 0.f;
            float sb = 0.f, b0 = 0.f, b1v = 0.f, b2v = 0.f, b3 = 0.f;

            #pragma unroll
            for (int k = 0; k < 16; k++) {
                acc_one(base[k],      sa, a0, a1, a2, a3);
                acc_one(base[17 + k], sb, b0, b1v, b2v, b3);
            }
            acc_one(base[16], sa, a0, a1, a2, a3);

            // merge two sorted-desc quads: top4 = sort(max(a_i, b_{3-i}))
            float u0 = fmaxf(a0, b3);
            float u1 = fmaxf(a1, b2v);
            float u2 = fmaxf(a2, b1v);
            float u3 = fmaxf(a3, b0);
            ce(u0, u2); ce(u1, u3); ce(u0, u1); ce(u2, u3);

            float inv = __frcp_rn(sa + sb);
            float p0 = u0 * inv, p1 = u1 * inv, p2 = u2 * inv, p3 = u3 * inv;
            float mean = 0.25f * ((p0 + p1) + (p2 + p3));

            float* so = sStat + lrow * 20 + 5 * g;
            so[0] = p0; so[1] = p1; so[2] = p2; so[3] = p3; so[4] = mean;
        }
    }
    __syncthreads();

    // ---------------- Phase B: MLP ----------------
    {
        const int warp = tid >> 5;
        const int lane = tid & 31;
        const int rh   = warp >> 2;        // row half: 0 or 1
        const int hq   = warp & 3;         // hidden quarter: 0..3
        const int mrow = rh * 32 + lane;

        float st[20];
        {
            const float* sr = sStat + mrow * 20;   // 16B-aligned, conflict-free LDS.128
            float4 q0 = *(const float4*)(sr + 0);
            float4 q1 = *(const float4*)(sr + 4);
            float4 q2 = *(const float4*)(sr + 8);
            float4 q3 = *(const float4*)(sr + 12);
            float4 q4 = *(const float4*)(sr + 16);
            st[0]  = q0.x; st[1]  = q0.y; st[2]  = q0.z; st[3]  = q0.w;
            st[4]  = q1.x; st[5]  = q1.y; st[6]  = q1.z; st[7]  = q1.w;
            st[8]  = q2.x; st[9]  = q2.y; st[10] = q2.z; st[11] = q2.w;
            st[12] = q3.x; st[13] = q3.y; st[14] = q3.z; st[15] = q3.w;
            st[16] = q4.x; st[17] = q4.y; st[18] = q4.z; st[19] = q4.w;
        }

        float q = 0.f;
        #pragma unroll
        for (int pass = 0; pass < 2; pass++) {
            const int h0 = hq * 16 + pass * 8;     // warp-uniform
            float acc[8];
            {
                float4 ba = *(const float4*)(sB1 + h0);
                float4 bb = *(const float4*)(sB1 + h0 + 4);
                acc[0] = ba.x; acc[1] = ba.y; acc[2] = ba.z; acc[3] = ba.w;
                acc[4] = bb.x; acc[5] = bb.y; acc[6] = bb.z; acc[7] = bb.w;
            }
            #pragma unroll
            for (int d = 0; d < 20; d++) {
                float sd = st[d];
                float4 wa = *(const float4*)(sW1 + d * 64 + h0);
                float4 wb = *(const float4*)(sW1 + d * 64 + h0 + 4);
                acc[0] += sd * wa.x; acc[1] += sd * wa.y;
                acc[2] += sd * wa.z; acc[3] += sd * wa.w;
                acc[4] += sd * wb.x; acc[5] += sd * wb.y;
                acc[6] += sd * wb.z; acc[7] += sd * wb.w;
            }
            {
                float4 wa = *(const float4*)(sW2 + h0);
                float4 wb = *(const float4*)(sW2 + h0 + 4);
                q += fmaxf(acc[0], 0.f) * wa.x;
                q += fmaxf(acc[1], 0.f) * wa.y;
                q += fmaxf(acc[2], 0.f) * wa.z;
                q += fmaxf(acc[3], 0.f) * wa.w;
                q += fmaxf(acc[4], 0.f) * wb.x;
                q += fmaxf(acc[5], 0.f) * wb.y;
                q += fmaxf(acc[6], 0.f) * wb.z;
                q += fmaxf(acc[7], 0.f) * wb.w;
            }
        }
        sQp[hq * 64 + mrow] = q;
    }
    __syncthreads();

    // ---------------- pre-reduce partials: sQv[row] = sum of 4 + b2 ----------------
    if (tid < 64) {
        sQv[tid] = (sQp[tid] + sQp[64 + tid]) + (sQp[128 + tid] + sQp[192 + tid]) + sB2;
    }
    __syncthreads();

    // ---------------- Phase C: out = scores + qv (streaming) ----------------
    {
        const float4* s4 = (const float4*)(scores + (size_t)row0 * 80);
        float4*       o4 = (float4*)(out + (size_t)row0 * 80);
        if (nr == 64) {                       // 1280 float4 = 5 * 256
            #pragma unroll
            for (int j = 0; j < 5; j++) {
                int i = j * 256 + tid;
                float qv = sQv[i / 20];
                float4 v = __ldcs(s4 + i);
                v.x += qv; v.y += qv; v.z += qv; v.w += qv;
                __stcs(o4 + i, v);
            }
        } else {
            int n4 = nr * 20;
            for (int i = tid; i < n4; i += 256) {
                float qv = sQv[i / 20];
                float4 v = __ldcs(s4 + i);
                v.x += qv; v.y += qv; v.z += qv; v.w += qv;
                __stcs(o4 + i, v);
            }
        }
    }
}

extern "C" void kernel_launch(void* const* d_in, const int* in_sizes, int n_in,
                              void* d_out, int out_size) {
    const float* scores  = (const float*)d_in[0];
    const float* corners = (const float*)d_in[1];
    const float* W1      = (const float*)d_in[2];
    const float* b1      = (const float*)d_in[3];
    const float* W2      = (const float*)d_in[4];
    const float* b2      = (const float*)d_in[5];
    float* out = (float*)d_out;

    int rows = in_sizes[0] / 80;              // B*L
    int blocks = (rows + 63) / 64;
    lqe_kernel<<<blocks, 256>>>(scores, corners, W1, b1, W2, b2, out, rows);
}

// round 17
// speedup vs baseline: 1.7258x; 1.1245x over previous
#include <cuda_runtime.h>

// Insert e into sorted (desc) top-4 registers t0>=t1>=t2>=t3.
__device__ __forceinline__ void ins4(float e, float& t0, float& t1, float& t2, float& t3)
{
    float c = e;
    float n0 = fmaxf(t0, c); c = fminf(t0, c);
    float n1 = fmaxf(t1, c); c = fminf(t1, c);
    float n2 = fmaxf(t2, c); c = fminf(t2, c);
    t3 = fmaxf(t3, c);
    t0 = n0; t1 = n1; t2 = n2;
}

__device__ __forceinline__ void acc_one(float v, float& s,
                                        float& t0, float& t1, float& t2, float& t3)
{
    float e = __expf(v);
    s += e;
    ins4(e, t0, t1, t2, t3);
}

__device__ __forceinline__ void ce(float& a, float& b) {
    float hi = fmaxf(a, b);
    float lo = fminf(a, b);
    a = hi; b = lo;
}

// Merge two sorted-desc quads, keep sorted top4 in a: bitonic split + 4-CE sort.
__device__ __forceinline__ void merge4(float& a0, float& a1, float& a2, float& a3,
                                       float b0, float b1, float b2, float b3)
{
    float u0 = fmaxf(a0, b3);
    float u1 = fmaxf(a1, b2);
    float u2 = fmaxf(a2, b1);
    float u3 = fmaxf(a3, b0);
    ce(u0, u2); ce(u1, u3); ce(u0, u1); ce(u2, u3);
    a0 = u0; a1 = u1; a2 = u2; a3 = u3;
}

// Block = 256 threads (8 warps) = 64 rows. (R13 structure: separate arrays, 4 CTAs/SM.)
//  Phase A: thread (row=tid>>2, g=tid&3): top4+sum for ONE group of 33 via FOUR
//           independent 8-value chains (4x ILP) + 3 quad-merges.
//           LDS bank (4r+g+k) mod 32 conflict-free. Stats -> sStat pitch 20.
//  Phase B: warp (rh=w>>2, hq=w&3): rows rh*32+lane, hidden [16hq,16hq+16), 2 passes of 8.
//  Phase C: coalesced float4: out = scores + sum of 4 hidden-quarter partials.
__global__ __launch_bounds__(256, 5)
void lqe_kernel(const float* __restrict__ scores,
                const float* __restrict__ corners,
                const float* __restrict__ gW1,
                const float* __restrict__ gb1,
                const float* __restrict__ gW2,
                const float* __restrict__ gb2,
                float* __restrict__ out,
                int rows)
{
    __shared__ __align__(16) float sC[64 * 132];     // 33792 B
    __shared__ __align__(16) float sW1[20 * 64];     //  5120 B
    __shared__ __align__(16) float sB1[64];
    __shared__ __align__(16) float sW2[64];
    __shared__ __align__(16) float sStat[64 * 20];   //  5120 B, pitch 20
    __shared__ float sQp[4 * 64];                    // per-hidden-quarter partials
    __shared__ float sB2;

    const int tid  = threadIdx.x;
    const int row0 = blockIdx.x * 64;
    const int nr   = min(64, rows - row0);

    // ---------------- stage corners (coalesced float4) ----------------
    {
        const float4* src = (const float4*)(corners + (size_t)row0 * 132);
        float4* dst = (float4*)sC;
        if (nr == 64) {                       // 2112 float4 = 8.25 * 256
            #pragma unroll
            for (int j = 0; j < 8; j++) dst[j * 256 + tid] = src[j * 256 + tid];
            if (tid < 64) dst[2048 + tid] = src[2048 + tid];
        } else {
            int n4 = nr * 33;
            for (int i = tid; i < n4; i += 256) dst[i] = src[i];
        }
    }
    // ---------------- stage weights ----------------
    {
        const float4* w4 = (const float4*)gW1;
        float4* d4 = (float4*)sW1;
        #pragma unroll
        for (int j = 0; j < 2; j++) {
            int idx = j * 256 + tid;
            if (idx < 320) d4[idx] = w4[idx];
        }
        if (tid < 64)        sB1[tid] = gb1[tid];
        else if (tid < 128)  sW2[tid - 64] = gW2[tid - 64];
        if (tid == 0)        sB2 = gb2[0];
    }
    __syncthreads();

    // ---------------- Phase A: 4 independent 8-value chains per thread ----------------
    {
        const int lrow = tid >> 2;
        const int g    = tid & 3;
        if (lrow < nr) {
            const float* base = sC + lrow * 132 + 33 * g;

            float sa = 0.f, a0 = 0.f, a1 = 0.f, a2 = 0.f, a3 = 0.f;
            float sb = 0.f, b0 = 0.f, b1 = 0.f, b2 = 0.f, b3 = 0.f;
            float sc = 0.f, c0 = 0.f, c1 = 0.f, c2 = 0.f, c3 = 0.f;
            float sd = 0.f, d0 = 0.f, d1 = 0.f, d2 = 0.f, d3 = 0.f;

            #pragma unroll
            for (int k = 0; k < 8; k++) {
                acc_one(base[k],      sa, a0, a1, a2, a3);
                acc_one(base[8 + k],  sb, b0, b1, b2, b3);
                acc_one(base[16 + k], sc, c0, c1, c2, c3);
                acc_one(base[24 + k], sd, d0, d1, d2, d3);
            }
            acc_one(base[32], sd, d0, d1, d2, d3);

            merge4(a0, a1, a2, a3, b0, b1, b2, b3);
            merge4(c0, c1, c2, c3, d0, d1, d2, d3);
            merge4(a0, a1, a2, a3, c0, c1, c2, c3);

            float inv = __frcp_rn((sa + sb) + (sc + sd));
            float p0 = a0 * inv, p1 = a1 * inv, p2 = a2 * inv, p3 = a3 * inv;
            float mean = 0.25f * ((p0 + p1) + (p2 + p3));

            float* so = sStat + lrow * 20 + 5 * g;
            so[0] = p0; so[1] = p1; so[2] = p2; so[3] = p3; so[4] = mean;
        }
    }
    __syncthreads();

    // ---------------- Phase B: MLP ----------------
    {
        const int warp = tid >> 5;
        const int lane = tid & 31;
        const int rh   = warp >> 2;        // row half: 0 or 1
        const int hq   = warp & 3;         // hidden quarter: 0..3
        const int mrow = rh * 32 + lane;

        float st[20];
        {
            const float* sr = sStat + mrow * 20;   // 16B-aligned, conflict-free LDS.128
            float4 q0 = *(const float4*)(sr + 0);
            float4 q1 = *(const float4*)(sr + 4);
            float4 q2 = *(const float4*)(sr + 8);
            float4 q3 = *(const float4*)(sr + 12);
            float4 q4 = *(const float4*)(sr + 16);
            st[0]  = q0.x; st[1]  = q0.y; st[2]  = q0.z; st[3]  = q0.w;
            st[4]  = q1.x; st[5]  = q1.y; st[6]  = q1.z; st[7]  = q1.w;
            st[8]  = q2.x; st[9]  = q2.y; st[10] = q2.z; st[11] = q2.w;
            st[12] = q3.x; st[13] = q3.y; st[14] = q3.z; st[15] = q3.w;
            st[16] = q4.x; st[17] = q4.y; st[18] = q4.z; st[19] = q4.w;
        }

        float q = (hq == 0) ? sB2 : 0.f;
        #pragma unroll
        for (int pass = 0; pass < 2; pass++) {
            const int h0 = hq * 16 + pass * 8;     // warp-uniform
            float acc[8];
            {
                float4 ba = *(const float4*)(sB1 + h0);
                float4 bb = *(const float4*)(sB1 + h0 + 4);
                acc[0] = ba.x; acc[1] = ba.y; acc[2] = ba.z; acc[3] = ba.w;
                acc[4] = bb.x; acc[5] = bb.y; acc[6] = bb.z; acc[7] = bb.w;
            }
            #pragma unroll
            for (int d = 0; d < 20; d++) {
                float sd = st[d];
                float4 wa = *(const float4*)(sW1 + d * 64 + h0);
                float4 wb = *(const float4*)(sW1 + d * 64 + h0 + 4);
                acc[0] += sd * wa.x; acc[1] += sd * wa.y;
                acc[2] += sd * wa.z; acc[3] += sd * wa.w;
                acc[4] += sd * wb.x; acc[5] += sd * wb.y;
                acc[6] += sd * wb.z; acc[7] += sd * wb.w;
            }
            {
                float4 wa = *(const float4*)(sW2 + h0);
                float4 wb = *(const float4*)(sW2 + h0 + 4);
                q += fmaxf(acc[0], 0.f) * wa.x;
                q += fmaxf(acc[1], 0.f) * wa.y;
                q += fmaxf(acc[2], 0.f) * wa.z;
                q += fmaxf(acc[3], 0.f) * wa.w;
                q += fmaxf(acc[4], 0.f) * wb.x;
                q += fmaxf(acc[5], 0.f) * wb.y;
                q += fmaxf(acc[6], 0.f) * wb.z;
                q += fmaxf(acc[7], 0.f) * wb.w;
            }
        }
        sQp[hq * 64 + mrow] = q;
    }
    __syncthreads();

    // ---------------- Phase C: out = scores + q ----------------
    {
        const float4* s4 = (const float4*)(scores + (size_t)row0 * 80);
        float4*       o4 = (float4*)(out + (size_t)row0 * 80);
        if (nr == 64) {                       // 1280 float4 = 5 * 256
            #pragma unroll
            for (int j = 0; j < 5; j++) {
                int i = j * 256 + tid;
                int r = i / 20;
                float qv = (sQp[r] + sQp[64 + r]) + (sQp[128 + r] + sQp[192 + r]);
                float4 v = s4[i];
                v.x += qv; v.y += qv; v.z += qv; v.w += qv;
                o4[i] = v;
            }
        } else {
            int n4 = nr * 20;
            for (int i = tid; i < n4; i += 256) {
                int r = i / 20;
                float qv = (sQp[r] + sQp[64 + r]) + (sQp[128 + r] + sQp[192 + r]);
                float4 v = s4[i];
                v.x += qv; v.y += qv; v.z += qv; v.w += qv;
                o4[i] = v;
            }
        }
    }
}

extern "C" void kernel_launch(void* const* d_in, const int* in_sizes, int n_in,
                              void* d_out, int out_size) {
    const float* scores  = (const float*)d_in[0];
    const float* corners = (const float*)d_in[1];
    const float* W1      = (const float*)d_in[2];
    const float* b1      = (const float*)d_in[3];
    const float* W2      = (const float*)d_in[4];
    const float* b2      = (const float*)d_in[5];
    float* out = (float*)d_out;

    int rows = in_sizes[0] / 80;              // B*L
    int blocks = (rows + 63) / 64;
    lqe_kernel<<<blocks, 256>>>(scores, corners, W1, b1, W2, b2, out, rows);
}